// round 1
// baseline (speedup 1.0000x reference)
#include <cuda_runtime.h>
#include <cuda_bf16.h>
#include <cstdint>

// ---------------------------------------------------------------------------
// PatchTransformer:
//   p = median7x7_reflect(adv_patch)          [3,300,300]
//   out[b,f] = clip(p * contrast[b,f] + brightness[b,f] + noise*0.1, 1e-6, 0.99999)
//
// Kernel 1: median filter -> __device__ scratch g_p
// Kernel 2: vectorized elementwise broadcast/affine/clip (HBM-bound)
// ---------------------------------------------------------------------------

#define PATCH 300
#define CH 3
#define BF_TOTAL (16 * 14)
#define PLANE (PATCH * PATCH)           // 90000
#define CHW (CH * PLANE)                // 270000

__device__ float g_p[CHW];

// compare-exchange: a <- min, b <- max
__device__ __forceinline__ void s2(float& a, float& b) {
    float t = fminf(a, b);
    b = fmaxf(a, b);
    a = t;
}

// Bring min of a[0..N-1] to a[0] and max to a[N-1]; multiset preserved.
template <int N>
__device__ __forceinline__ void mnmx(float* a) {
#pragma unroll
    for (int i = 0; i < N / 2; i++) s2(a[i], a[N - 1 - i]);
#pragma unroll
    for (int i = 1; i < (N + 1) / 2; i++) s2(a[0], a[i]);
#pragma unroll
    for (int i = N - 2; i >= N / 2; i--) s2(a[i], a[N - 1]);
}

__device__ __forceinline__ int reflect_idx(int t) {
    // jnp.pad 'reflect' (mirror without repeating border), H = 300
    t = (t < 0) ? -t : t;
    t = (t >= PATCH) ? (2 * PATCH - 2 - t) : t;
    return t;
}

// Tile: 32x8 outputs per block, halo 3 -> load 38x14.
#define TBX 32
#define TBY 8
#define TILE_W (TBX + 6)   // 38
#define TILE_H (TBY + 6)   // 14
#define TILE_PITCH 40      // padded row stride (floats)

__global__ __launch_bounds__(TBX * TBY)
void median7_kernel(const float* __restrict__ src) {
    __shared__ float tile[TILE_H][TILE_PITCH];

    const int c  = blockIdx.z;
    const int x0 = blockIdx.x * TBX;
    const int y0 = blockIdx.y * TBY;
    const float* s = src + c * PLANE;

    const int tid = threadIdx.y * TBX + threadIdx.x;
#pragma unroll
    for (int i = tid; i < TILE_W * TILE_H; i += TBX * TBY) {
        const int lx = i % TILE_W;
        const int ly = i / TILE_W;
        const int gx = reflect_idx(x0 - 3 + lx);
        const int gy = reflect_idx(y0 - 3 + ly);
        tile[ly][lx] = s[gy * PATCH + gx];
    }
    __syncthreads();

    const int tx = threadIdx.x;
    const int ty = threadIdx.y;
    const int ox = x0 + tx;
    const int oy = y0 + ty;
    if (ox >= PATCH || oy >= PATCH) return;

    // ---- forgetful median selection over the 7x7 window ----
    float a[26];
#pragma unroll
    for (int k = 0; k < 26; k++)
        a[k] = tile[ty + k / 7][tx + k % 7];

    // 11 steps: discard min & max of 26-set, feed 2 new values
#pragma unroll
    for (int st = 0; st < 11; st++) {
        mnmx<26>(a);
        const int k0 = 26 + 2 * st;
        const int k1 = 27 + 2 * st;
        a[0]  = tile[ty + k0 / 7][tx + k0 % 7];
        a[25] = tile[ty + k1 / 7][tx + k1 % 7];
    }
    // final step: discard both, feed last value (index 48) -> set is a[0..24]
    mnmx<26>(a);
    a[0] = tile[ty + 48 / 7][tx + 48 % 7];

    // Now: 25 values, target rank = 12 (0-based). Symmetric shrink.
    mnmx<25>(a);
    mnmx<23>(a + 1);
    mnmx<21>(a + 2);
    mnmx<19>(a + 3);
    mnmx<17>(a + 4);
    mnmx<15>(a + 5);
    mnmx<13>(a + 6);
    mnmx<11>(a + 7);
    mnmx<9>(a + 8);
    mnmx<7>(a + 9);
    mnmx<5>(a + 10);
    // median of a[11], a[12], a[13] -> a[12]
    s2(a[11], a[12]);
    s2(a[12], a[13]);
    s2(a[11], a[12]);

    g_p[c * PLANE + oy * PATCH + ox] = a[12];
}

// ---------------------------------------------------------------------------
// Elementwise: out = clip(p*c + br + noise*0.1)
// Vectorized by float4; 270000 % 4 == 0 so a vec4 never crosses a (b,f) slab.
// ---------------------------------------------------------------------------
__global__ __launch_bounds__(256)
void apply_kernel(const float4* __restrict__ noise,
                  const float* __restrict__ contrast,
                  const float* __restrict__ brightness,
                  float4* __restrict__ out,
                  int total4) {
    const int i = blockIdx.x * blockDim.x + threadIdx.x;
    if (i >= total4) return;

    const unsigned flat = (unsigned)i * 4u;
    const unsigned bf   = flat / (unsigned)CHW;       // mul-shift by compiler
    const unsigned rem  = flat - bf * (unsigned)CHW;  // multiple of 4

    const float c  = __ldg(&contrast[bf]);
    const float br = __ldg(&brightness[bf]);

    const float4 n = noise[i];
    const float4 p = *reinterpret_cast<const float4*>(&g_p[rem]);

    float4 r;
    r.x = fmaf(n.x, 0.1f, fmaf(p.x, c, br));
    r.y = fmaf(n.y, 0.1f, fmaf(p.y, c, br));
    r.z = fmaf(n.z, 0.1f, fmaf(p.z, c, br));
    r.w = fmaf(n.w, 0.1f, fmaf(p.w, c, br));

    r.x = fminf(fmaxf(r.x, 1e-6f), 0.99999f);
    r.y = fminf(fmaxf(r.y, 1e-6f), 0.99999f);
    r.z = fminf(fmaxf(r.z, 1e-6f), 0.99999f);
    r.w = fminf(fmaxf(r.w, 1e-6f), 0.99999f);

    out[i] = r;
}

// ---------------------------------------------------------------------------
// Inputs (metadata order):
//   0: adv_patch  [3,300,300] f32   (270000)
//   1: lab_batch  [16,14,5]   f32   (unused)
//   2: contrast   [16,14]     f32   (224)
//   3: brightness [16,14]     f32   (224)
//   4: noise      [16,14,3,300,300] f32 (60480000)
//   5: img_size   scalar (unused)
// Output: [16,14,3,300,300] f32
// ---------------------------------------------------------------------------
extern "C" void kernel_launch(void* const* d_in, const int* in_sizes, int n_in,
                              void* d_out, int out_size) {
    const float* adv_patch  = (const float*)d_in[0];
    const float* contrast   = (const float*)d_in[2];
    const float* brightness = (const float*)d_in[3];
    const float* noise      = (const float*)d_in[4];
    float* out = (float*)d_out;

    dim3 mblk(TBX, TBY, 1);
    dim3 mgrd((PATCH + TBX - 1) / TBX, (PATCH + TBY - 1) / TBY, CH);
    median7_kernel<<<mgrd, mblk>>>(adv_patch);

    const int total4 = (BF_TOTAL * CHW) / 4;   // 15,120,000
    const int threads = 256;
    const int blocks = (total4 + threads - 1) / threads;
    apply_kernel<<<blocks, threads>>>((const float4*)noise, contrast, brightness,
                                      (float4*)out, total4);
}